// round 4
// baseline (speedup 1.0000x reference)
#include <cuda_runtime.h>

// out[b,i,j,d] = x[b,i,j,d] + W[d, bin] + bias[d],  bin = clip(i-j,-31,31)+31
// B=2, L=512, D=128. x/out: 256 MB each (fp32). Pure HBM stream.
//
// Inputs (metadata order): d_in[0]=x (f32), d_in[1]=idx (i64, unused),
//                          d_in[2]=W (f32 [128,63]), d_in[3]=b (f32 [128])
//
// R3: coalesced single-block prep (was 128-way uncoalesced, ~8us overhead),
//     VPT=8 front-batched loads in the main stream kernel.

#define L_DIM   512
#define D_DIM   128
#define NBINS   63
#define TOTAL_F4 (2 * L_DIM * L_DIM * (D_DIM / 4))   // 16,777,216
#define VPT 8                                         // float4 per thread
#define TPB 256

// Scratch table: relemb[bin][d] = W[d][bin] + b[d]  (63*128 floats = 32 KB)
__device__ float4 g_relemb[NBINS * (D_DIM / 4)];

// Single block, coalesced linear reads of W (8064 floats), scattered 4B
// writes into the tiny table. bias (128 floats) hits L1 after first touch.
__global__ __launch_bounds__(1024)
void build_relemb_kernel(const float* __restrict__ W,
                         const float* __restrict__ bias) {
    for (int t = threadIdx.x; t < NBINS * D_DIM; t += 1024) {
        int d   = t / NBINS;          // W is [128, 63] row-major
        int bin = t - d * NBINS;
        float v = W[t] + bias[d];
        reinterpret_cast<float*>(g_relemb)[bin * D_DIM + d] = v;
    }
}

__global__ __launch_bounds__(TPB)
void add_rel_kernel(const float4* __restrict__ x, float4* __restrict__ out) {
    int base = blockIdx.x * (TPB * VPT) + threadIdx.x;

    // Front-batch 8 independent global loads (MLP=8 per thread).
    float4 xv[VPT];
    #pragma unroll
    for (int k = 0; k < VPT; k++)
        xv[k] = __ldcs(&x[base + k * TPB]);

    float4 rv[VPT];
    #pragma unroll
    for (int k = 0; k < VPT; k++) {
        int g   = base + k * TPB;
        int d4  = g & 31;
        int row = g >> 5;                         // b*L*L + i*L + j
        int j   = row & (L_DIM - 1);
        int i   = (row >> 9) & (L_DIM - 1);
        int rel = i - j;
        rel = max(-(NBINS / 2), min(NBINS / 2, rel));
        int bin = rel + NBINS / 2;                // 0..62
        rv[k] = g_relemb[bin * 32 + d4];          // L1-resident table hit
    }

    #pragma unroll
    for (int k = 0; k < VPT; k++) {
        float4 ov;
        ov.x = xv[k].x + rv[k].x;
        ov.y = xv[k].y + rv[k].y;
        ov.z = xv[k].z + rv[k].z;
        ov.w = xv[k].w + rv[k].w;
        __stcs(&out[base + k * TPB], ov);
    }
}

extern "C" void kernel_launch(void* const* d_in, const int* in_sizes, int n_in,
                              void* d_out, int out_size) {
    const float* x    = (const float*)d_in[0];
    const float* W    = (const float*)d_in[2];
    const float* bias = (const float*)d_in[3];
    float* out        = (float*)d_out;

    build_relemb_kernel<<<1, 1024>>>(W, bias);

    add_rel_kernel<<<TOTAL_F4 / (TPB * VPT), TPB>>>(
        (const float4*)x, (float4*)out);
}